// round 3
// baseline (speedup 1.0000x reference)
#include <cuda_runtime.h>
#include <cstddef>

#define NN 2048
#define EE 32
#define R2F 0.0025f   // float32(0.05^2), matches JAX's weak-typed scalar promotion

// Sparse pass: one block per source node s (grid=2048, block=256).
// Thread t scans dsts t, t+256, ... (8 each). Only valid edges (~0.8%)
// compute the MLP and write their 128B feature row. The 512MB zero fill
// is done by the preceding cudaMemsetAsync graph node.
__global__ void __launch_bounds__(256)
sparse_edges_kernel(const float* __restrict__ pos,
                    const float* __restrict__ W1,
                    const float* __restrict__ b1,
                    const float* __restrict__ W2,
                    const float* __restrict__ b2,
                    float4* __restrict__ out) {
    __shared__ float4 sW1p[32];    // packed {W1x, W1y, b1, 0}
    __shared__ float4 sW2[256];    // W2[32][32] as 32 rows x 8 float4
    __shared__ float4 sb2[8];

    const int tid = threadIdx.x;
    if (tid < 32) sW1p[tid] = make_float4(W1[tid], W1[32 + tid], b1[tid], 0.0f);
    sW2[tid] = ((const float4*)W2)[tid];
    if (tid < 8) sb2[tid] = ((const float4*)b2)[tid];
    __syncthreads();

    const int s = blockIdx.x;
    const float2 ps = ((const float2*)pos)[s];

#pragma unroll
    for (int k = 0; k < NN / 256; k++) {
        const int d = k * 256 + tid;                  // coalesced pos reads
        const float2 pd = ((const float2*)pos)[d];
        const float rx = pd.x - ps.x;                 // pos[dst] - pos[src]
        const float ry = pd.y - ps.y;
        // no-FMA dist2: bit-exact with jnp (mul, mul, add in f32)
        const float d2 = __fadd_rn(__fmul_rn(rx, rx), __fmul_rn(ry, ry));
        if (d2 <= R2F && d != s) {
            // hidden layer: 32 units
            float h[32];
#pragma unroll
            for (int j = 0; j < 32; j++) {
                float4 w1 = sW1p[j];
                h[j] = fmaxf(fmaf(ry, w1.y, fmaf(rx, w1.x, w1.z)), 0.0f);
            }
            float4* o = out + ((size_t)s * NN + (size_t)d) * (EE / 4);
#pragma unroll
            for (int eb = 0; eb < 8; eb++) {
                float4 acc = sb2[eb];
#pragma unroll
                for (int j = 0; j < 32; j++) {
                    float4 w2 = sW2[j * 8 + eb];      // W2[j][4eb..4eb+3]
                    acc.x = fmaf(h[j], w2.x, acc.x);
                    acc.y = fmaf(h[j], w2.y, acc.y);
                    acc.z = fmaf(h[j], w2.z, acc.z);
                    acc.w = fmaf(h[j], w2.w, acc.w);
                }
                o[eb] = acc;
            }
        }
    }
}

// Inputs (metadata order): node_features (unused), object_positions_2d,
// W1, b1, W2, b2. Output: edge_attr [N, N, E] fp32.
extern "C" void kernel_launch(void* const* d_in, const int* in_sizes, int n_in,
                              void* d_out, int out_size) {
    const float* pos = (const float*)d_in[1];
    const float* W1  = (const float*)d_in[2];
    const float* b1  = (const float*)d_in[3];
    const float* W2  = (const float*)d_in[4];
    const float* b2  = (const float*)d_in[5];
    // Driver memset zero-fills all 512MB (capturable memset node, no alloc).
    cudaMemsetAsync(d_out, 0, (size_t)out_size * sizeof(float), 0);
    sparse_edges_kernel<<<NN, 256>>>(pos, W1, b1, W2, b2, (float4*)d_out);
}

// round 4
// speedup vs baseline: 4.8174x; 4.8174x over previous
#include <cuda_runtime.h>
#include <cstddef>

#define NN 2048
#define EE 32
#define R2F 0.0025f   // float32(0.05^2), matches JAX's weak-typed scalar promotion

// Rare path: 2-layer MLP for one valid edge; this lane produces output
// features [4*eb, 4*eb+4). Weights pre-staged in shared memory as float4.
__device__ __noinline__ float4 edge_mlp(float rx, float ry,
                                        const float4* __restrict__ sW1p,
                                        const float4* __restrict__ sW2,
                                        const float4* __restrict__ sb2,
                                        int eb) {
    float4 acc = sb2[eb];
#pragma unroll 8
    for (int j = 0; j < 32; j++) {
        float4 w1 = sW1p[j];                         // {W1[0][j], W1[1][j], b1[j], 0}
        float h = fmaf(ry, w1.y, fmaf(rx, w1.x, w1.z));
        h = fmaxf(h, 0.0f);
        float4 w2 = sW2[j * 8 + eb];                 // W2[j][4eb .. 4eb+3]
        acc.x = fmaf(h, w2.x, acc.x);
        acc.y = fmaf(h, w2.y, acc.y);
        acc.z = fmaf(h, w2.z, acc.z);
        acc.w = fmaf(h, w2.w, acc.w);
    }
    return acc;
}

// Slow path for one 32-dst chunk with a nonzero validity mask.
__device__ __forceinline__ void chunk_with_edges(unsigned mask, float rx, float ry,
                                                 float4* __restrict__ o,
                                                 int lane, int grp, int eb,
                                                 const float4* __restrict__ sW1p,
                                                 const float4* __restrict__ sW2,
                                                 const float4* __restrict__ sb2) {
    const float4 zero4 = make_float4(0.0f, 0.0f, 0.0f, 0.0f);
#pragma unroll 1
    for (int i = 0; i < 8; i++) {
        const unsigned m4 = (mask >> (i * 4)) & 0xFu;   // warp-uniform
        float4 v = zero4;
        if (m4) {
            const int src = i * 4 + grp;
            const float frx = __shfl_sync(0xffffffffu, rx, src);
            const float fry = __shfl_sync(0xffffffffu, ry, src);
            if ((m4 >> grp) & 1u)
                v = edge_mlp(frx, fry, sW1p, sW2, sb2, eb);
        }
        o[i * 32 + lane] = v;
    }
}

// One block per source node s (grid = 2048, block = 256 = 8 warps).
// Each warp processes 64-dst double-chunks (c = warp, warp+8, ...).
// Two ballots per double-chunk; both-zero (~61%) takes a branch-free
// 16x STG.128 path — 8KB contiguous per warp, deep store pipeline.
__global__ void __launch_bounds__(256)
graph_edges_kernel(const float* __restrict__ pos,
                   const float* __restrict__ W1,
                   const float* __restrict__ b1,
                   const float* __restrict__ W2,
                   const float* __restrict__ b2,
                   float4* __restrict__ out) {
    __shared__ float4 sW1p[32];    // packed {W1x, W1y, b1, 0}
    __shared__ float4 sW2[256];    // W2[32][32] as 32 rows x 8 float4
    __shared__ float4 sb2[8];

    const int tid = threadIdx.x;
    if (tid < 32) sW1p[tid] = make_float4(W1[tid], W1[32 + tid], b1[tid], 0.0f);
    sW2[tid] = ((const float4*)W2)[tid];             // 256 float4 = 1024 floats
    if (tid < 8) sb2[tid] = ((const float4*)b2)[tid];
    __syncthreads();

    const int lane = tid & 31;
    const int warp = tid >> 5;
    const int grp  = lane >> 3;    // which of 4 pairs in a store iteration
    const int eb   = lane & 7;     // which float4 of the 32 features
    const int s    = blockIdx.x;

    const float2* pos2 = (const float2*)pos;
    const float2 ps = pos2[s];
    const float4 zero4 = make_float4(0.0f, 0.0f, 0.0f, 0.0f);

    for (int c = warp; c < NN / 64; c += 8) {
        const int d0 = c * 64;
        const float2 pa = pos2[d0 + lane];
        const float2 pb = pos2[d0 + 32 + lane];
        const float rx0 = pa.x - ps.x, ry0 = pa.y - ps.y;   // pos[dst]-pos[src]
        const float rx1 = pb.x - ps.x, ry1 = pb.y - ps.y;
        // no-FMA dist2: bit-exact with jnp (mul, mul, add in f32)
        const float d2a = __fadd_rn(__fmul_rn(rx0, rx0), __fmul_rn(ry0, ry0));
        const float d2b = __fadd_rn(__fmul_rn(rx1, rx1), __fmul_rn(ry1, ry1));
        const bool va = (d2a <= R2F) && ((d0 + lane) != s);
        const bool vb = (d2b <= R2F) && ((d0 + 32 + lane) != s);
        const unsigned mask0 = __ballot_sync(0xffffffffu, va);
        const unsigned mask1 = __ballot_sync(0xffffffffu, vb);

        float4* o = out + ((size_t)s * NN + (size_t)d0) * (EE / 4);

        if ((mask0 | mask1) == 0u) {
            // ~61% of double-chunks: 16 back-to-back coalesced STG.128.
#pragma unroll
            for (int i = 0; i < 16; i++)
                o[i * 32 + lane] = zero4;
        } else {
            if (mask0 == 0u) {
#pragma unroll
                for (int i = 0; i < 8; i++) o[i * 32 + lane] = zero4;
            } else {
                chunk_with_edges(mask0, rx0, ry0, o, lane, grp, eb, sW1p, sW2, sb2);
            }
            float4* o1 = o + 256;
            if (mask1 == 0u) {
#pragma unroll
                for (int i = 0; i < 8; i++) o1[i * 32 + lane] = zero4;
            } else {
                chunk_with_edges(mask1, rx1, ry1, o1, lane, grp, eb, sW1p, sW2, sb2);
            }
        }
    }
}

// Inputs (metadata order): node_features (unused), object_positions_2d,
// W1, b1, W2, b2. Output: edge_attr [N, N, E] fp32.
extern "C" void kernel_launch(void* const* d_in, const int* in_sizes, int n_in,
                              void* d_out, int out_size) {
    const float* pos = (const float*)d_in[1];
    const float* W1  = (const float*)d_in[2];
    const float* b1  = (const float*)d_in[3];
    const float* W2  = (const float*)d_in[4];
    const float* b2  = (const float*)d_in[5];
    graph_edges_kernel<<<NN, 256>>>(pos, W1, b1, W2, b2, (float4*)d_out);
}